// round 3
// baseline (speedup 1.0000x reference)
#include <cuda_runtime.h>
#include <math.h>

// Problem constants
#define TOKENS 4096L   // B*T
#define TSEQ   1024
#define CDIM   1024
#define NHEAD  16
#define NKV    4
#define HDIM   64
#define FFNH   4096

// ---------------- scratch (device globals; no allocation allowed) -----------
__device__ float g_xn   [TOKENS*CDIM];
__device__ float g_q    [TOKENS*CDIM];
__device__ float g_k    [TOKENS*256];
__device__ float g_v    [TOKENS*256];
__device__ float g_att  [64L*1024*1024];   // (B*NH, T, T) = 256MB
__device__ float g_y    [TOKENS*CDIM];
__device__ float g_ao   [TOKENS*CDIM];
__device__ float g_cah  [TOKENS*32];
__device__ float g_cah2 [TOKENS*32];
__device__ float g_caout[TOKENS*CDIM];
__device__ float g_x1   [TOKENS*CDIM];
__device__ float g_xm   [TOKENS*CDIM];
__device__ float g_ffh  [TOKENS*FFNH];
__device__ float g_ffh2 [TOKENS*FFNH];
__device__ float g_gate2[TOKENS*CDIM];
__device__ float g_mlp  [TOKENS*CDIM];
__device__ float g_h32  [TOKENS*32];
__device__ float g_vit  [TOKENS];
__device__ float g_vitf [TOKENS];

// ---------------- rmsnorm: one block per row of C=1024 ----------------------
__global__ void rmsnorm_kernel(const float* __restrict__ x, float* __restrict__ o) {
    long row = blockIdx.x;
    const float* xr = x + row * CDIM;
    float* orow = o + row * CDIM;
    float ss = 0.f;
    for (int i = threadIdx.x; i < CDIM; i += 256) { float v = xr[i]; ss += v * v; }
    __shared__ float sh[256];
    sh[threadIdx.x] = ss; __syncthreads();
    for (int s = 128; s > 0; s >>= 1) { if (threadIdx.x < s) sh[threadIdx.x] += sh[threadIdx.x + s]; __syncthreads(); }
    float scale = rsqrtf(sh[0] / (float)CDIM + 1e-6f);
    for (int i = threadIdx.x; i < CDIM; i += 256) orow[i] = xr[i] * scale;
}

// ---------------- generic GEMM: C[M,N] = A[M,K] * W[N,K]^T + epilogue -------
// mode: 0 none, 1 relu^2, 2 sigmoid, 3 gelu(exact), 4 multiply-by-aux
__global__ void gemm_nt_kernel(const float* __restrict__ A, const float* __restrict__ W,
                               float* __restrict__ C, int M, int N, int K,
                               int mode, const float* __restrict__ aux) {
    __shared__ float As[16][65];  // [k][m]
    __shared__ float Ws[16][65];  // [k][n]
    int bm = blockIdx.y * 64, bn = blockIdx.x * 64;
    int tid = threadIdx.x;
    int tx = tid & 15, ty = tid >> 4;
    float acc[4][4] = {};
    for (int k0 = 0; k0 < K; k0 += 16) {
        int kk = tid & 15;
        int r0 = tid >> 4;
        #pragma unroll
        for (int i = 0; i < 4; i++) {
            int m = r0 + 16 * i; int gm = bm + m;
            As[kk][m] = (gm < M) ? A[(long)gm * K + k0 + kk] : 0.f;
        }
        #pragma unroll
        for (int i = 0; i < 4; i++) {
            int n = r0 + 16 * i; int gn = bn + n;
            Ws[kk][n] = (gn < N) ? W[(long)gn * K + k0 + kk] : 0.f;
        }
        __syncthreads();
        #pragma unroll
        for (int k = 0; k < 16; k++) {
            float a[4], b[4];
            #pragma unroll
            for (int i = 0; i < 4; i++) a[i] = As[k][ty * 4 + i];
            #pragma unroll
            for (int j = 0; j < 4; j++) b[j] = Ws[k][tx * 4 + j];
            #pragma unroll
            for (int i = 0; i < 4; i++)
                #pragma unroll
                for (int j = 0; j < 4; j++) acc[i][j] += a[i] * b[j];
        }
        __syncthreads();
    }
    #pragma unroll
    for (int i = 0; i < 4; i++) {
        int gm = bm + ty * 4 + i; if (gm >= M) continue;
        #pragma unroll
        for (int j = 0; j < 4; j++) {
            int gn = bn + tx * 4 + j; if (gn >= N) continue;
            float v = acc[i][j];
            if (mode == 1)      { float r = fmaxf(v, 0.f); v = r * r; }
            else if (mode == 2) { v = 1.f / (1.f + __expf(-v)); }
            else if (mode == 3) { v = 0.5f * v * (1.f + erff(v * 0.70710678118654752f)); }
            else if (mode == 4) { v *= aux[(long)gm * N + gn]; }
            C[(long)gm * N + gn] = v;
        }
    }
}

// ---------------- ve gate fuse: v += 3*sigmoid(xn[:,:12]@wg^T) * ve ---------
__global__ void vegate_kernel(const float* __restrict__ xn, const float* __restrict__ ve,
                              const float* __restrict__ wg, float* __restrict__ v) {
    long tok = blockIdx.x;
    __shared__ float g[4];
    __shared__ float xv[12];
    if (threadIdx.x < 12) xv[threadIdx.x] = xn[tok * CDIM + threadIdx.x];
    __syncthreads();
    if (threadIdx.x < 4) {
        float s = 0.f;
        #pragma unroll
        for (int j = 0; j < 12; j++) s += xv[j] * wg[threadIdx.x * 12 + j];
        g[threadIdx.x] = 3.f / (1.f + expf(-s));
    }
    __syncthreads();
    int i = threadIdx.x;  // 0..255
    v[tok * 256 + i] += g[i >> 6] * ve[tok * 256 + i];
}

// ---------------- rope + rmsnorm(HD=64) * 1.2, one warp per (token,head) ----
__global__ void rope_rms_kernel(float* __restrict__ q, const float* __restrict__ cosb,
                                const float* __restrict__ sinb, int nh) {
    long idx = (long)blockIdx.x * 8 + (threadIdx.x >> 5);
    long total = TOKENS * nh;
    if (idx >= total) return;
    int lane = threadIdx.x & 31;
    long tok = idx / nh; int h = (int)(idx % nh);
    int t = (int)(tok & 1023);
    float* p = q + (tok * nh + h) * 64;
    float x1 = p[lane], x2 = p[lane + 32];
    float c = cosb[t * 32 + lane], s = sinb[t * 32 + lane];
    float r1 =  x1 * c + x2 * s;
    float r2 = -x1 * s + x2 * c;
    float ss = r1 * r1 + r2 * r2;
    #pragma unroll
    for (int o = 16; o > 0; o >>= 1) ss += __shfl_xor_sync(0xffffffffu, ss, o);
    float sc = rsqrtf(ss / 64.f + 1e-6f) * 1.2f;
    p[lane] = r1 * sc; p[lane + 32] = r2 * sc;
}

// ---------------- attention scores: qk/8 + alpha*conv3x3(prev) + mask -------
__global__ void attn_score_kernel(const float* __restrict__ q, const float* __restrict__ k,
                                  const float* __restrict__ prev, const float* __restrict__ rw,
                                  const float* __restrict__ alphap, float* __restrict__ att) {
    int bh = blockIdx.z; int b = bh >> 4, h = bh & 15;
    int qt0 = blockIdx.y * 64, kt0 = blockIdx.x * 64;
    int tid = threadIdx.x, tx = tid & 15, ty = tid >> 4;
    long base = (long)bh * 1024 * 1024;
    if (kt0 > qt0 + 63) {  // fully masked tile
        for (int i = tid; i < 64 * 64; i += 256) {
            int qi = i >> 6, kj = i & 63;
            att[base + (long)(qt0 + qi) * 1024 + kt0 + kj] = -1e30f;
        }
        return;
    }
    __shared__ float smem[2 * 64 * 65];
    // Qs(r,d)=smem[r*65+d], Ks(r,d)=smem[64*65 + r*65+d]
    for (int i = tid; i < 64 * 64; i += 256) {
        int r = i >> 6, d = i & 63;
        smem[r * 65 + d] = q[((long)(b * 1024 + qt0 + r) * 16 + h) * 64 + d];
    }
    int kvh = h >> 2;
    for (int i = tid; i < 64 * 64; i += 256) {
        int r = i >> 6, d = i & 63;
        smem[64 * 65 + r * 65 + d] = k[((long)(b * 1024 + kt0 + r) * 4 + kvh) * 64 + d];
    }
    __syncthreads();
    float acc[4][4] = {};
    #pragma unroll 8
    for (int kk = 0; kk < 64; kk++) {
        float a[4], bv[4];
        #pragma unroll
        for (int i = 0; i < 4; i++) a[i]  = smem[(ty * 4 + i) * 65 + kk];
        #pragma unroll
        for (int j = 0; j < 4; j++) bv[j] = smem[64 * 65 + (tx * 4 + j) * 65 + kk];
        #pragma unroll
        for (int i = 0; i < 4; i++)
            #pragma unroll
            for (int j = 0; j < 4; j++) acc[i][j] += a[i] * bv[j];
    }
    __syncthreads();
    // reuse shared for prev_attn halo tile 66x66 (stride 67)
    for (int i = tid; i < 66 * 66; i += 256) {
        int ii = i / 66, jj = i % 66;
        int gq = qt0 - 1 + ii, gk = kt0 - 1 + jj;
        float pv = (gq >= 0 && gq < 1024 && gk >= 0 && gk < 1024)
                       ? prev[base + (long)gq * 1024 + gk] : 0.f;
        smem[ii * 67 + jj] = pv;
    }
    __syncthreads();
    float w9[9];
    #pragma unroll
    for (int i = 0; i < 9; i++) w9[i] = rw[h * 9 + i];
    float alpha = alphap[0];
    #pragma unroll
    for (int i = 0; i < 4; i++) {
        int ql = ty * 4 + i;
        #pragma unroll
        for (int j = 0; j < 4; j++) {
            int kl = tx * 4 + j;
            float conv = 0.f;
            #pragma unroll
            for (int di = 0; di < 3; di++)
                #pragma unroll
                for (int dj = 0; dj < 3; dj++)
                    conv += smem[(ql + di) * 67 + kl + dj] * w9[di * 3 + dj];
            float sv = acc[i][j] * 0.125f + alpha * conv;
            int gq = qt0 + ql, gk = kt0 + kl;
            if (gk > gq) sv = -1e30f;
            att[base + (long)gq * 1024 + gk] = sv;
        }
    }
}

// ---------------- row softmax over 1024 -------------------------------------
__global__ void softmax_kernel(float* __restrict__ att) {
    long row = blockIdx.x;
    float* p = att + row * 1024;
    __shared__ float sh[256];
    float m = -1e30f;
    for (int i = threadIdx.x; i < 1024; i += 256) m = fmaxf(m, p[i]);
    sh[threadIdx.x] = m; __syncthreads();
    for (int s = 128; s > 0; s >>= 1) { if (threadIdx.x < s) sh[threadIdx.x] = fmaxf(sh[threadIdx.x], sh[threadIdx.x + s]); __syncthreads(); }
    m = sh[0]; __syncthreads();
    float sum = 0.f;
    for (int i = threadIdx.x; i < 1024; i += 256) {
        float e = __expf(p[i] - m);
        p[i] = e; sum += e;
    }
    sh[threadIdx.x] = sum; __syncthreads();
    for (int s = 128; s > 0; s >>= 1) { if (threadIdx.x < s) sh[threadIdx.x] += sh[threadIdx.x + s]; __syncthreads(); }
    float inv = 1.f / sh[0];
    for (int i = threadIdx.x; i < 1024; i += 256) p[i] *= inv;
}

// ---------------- y = aw @ v  (exploits causality: k <= qt0+63) -------------
__global__ void attn_av_kernel(const float* __restrict__ aw, const float* __restrict__ v,
                               float* __restrict__ y) {
    int bh = blockIdx.y; int b = bh >> 4, h = bh & 15; int kvh = h >> 2;
    int qt0 = blockIdx.x * 64;
    long base = (long)bh * 1024 * 1024;
    __shared__ float As[64][17];  // aw [m][k-chunk]
    __shared__ float Bs[16][65];  // v  [k][d]
    int tid = threadIdx.x, tx = tid & 15, ty = tid >> 4;
    float acc[4][4] = {};
    int kmax = qt0 + 64;  // rows in this tile have zero weight beyond q <= qt0+63
    for (int k0 = 0; k0 < kmax; k0 += 16) {
        {
            int kk = tid & 15, m0 = tid >> 4;
            #pragma unroll
            for (int i = 0; i < 4; i++) {
                int m = m0 + 16 * i;
                As[m][kk] = aw[base + (long)(qt0 + m) * 1024 + k0 + kk];
            }
        }
        {
            int d = tid & 63, r0 = tid >> 6;
            #pragma unroll
            for (int i = 0; i < 4; i++) {
                int r = r0 + 4 * i;
                Bs[r][d] = v[((long)(b * 1024 + k0 + r) * 4 + kvh) * 64 + d];
            }
        }
        __syncthreads();
        #pragma unroll
        for (int kk = 0; kk < 16; kk++) {
            float a[4], bv[4];
            #pragma unroll
            for (int i = 0; i < 4; i++) a[i]  = As[ty * 4 + i][kk];
            #pragma unroll
            for (int j = 0; j < 4; j++) bv[j] = Bs[kk][tx * 4 + j];
            #pragma unroll
            for (int i = 0; i < 4; i++)
                #pragma unroll
                for (int j = 0; j < 4; j++) acc[i][j] += a[i] * bv[j];
        }
        __syncthreads();
    }
    #pragma unroll
    for (int i = 0; i < 4; i++)
        #pragma unroll
        for (int j = 0; j < 4; j++)
            y[((long)(b * 1024 + qt0 + ty * 4 + i) * 16 + h) * 64 + tx * 4 + j] = acc[i][j];
}

// ---------------- CA: h += 0.1*tconv3, then exact gelu (32 channels) --------
__global__ void ca_conv_gelu_kernel(const float* __restrict__ in, const float* __restrict__ w,
                                    float* __restrict__ out) {
    long idx = (long)blockIdx.x * 256 + threadIdx.x;
    if (idx >= TOKENS * 32) return;
    int c = (int)(idx & 31);
    long bt = idx >> 5; int t = (int)(bt & 1023);
    float cur = in[idx];
    float pv = (t > 0)    ? in[idx - 32] : 0.f;
    float nx = (t < 1023) ? in[idx + 32] : 0.f;
    float h = cur + 0.1f * (pv * w[c * 3] + cur * w[c * 3 + 1] + nx * w[c * 3 + 2]);
    out[idx] = 0.5f * h * (1.f + erff(h * 0.70710678118654752f));
}

// ---------------- FFN temporal conv pass: out = in + 0.1*tconv3(in) ---------
__global__ void ffn_tconv_kernel(const float* __restrict__ in, const float* __restrict__ w,
                                 float* __restrict__ out) {
    long idx = (long)blockIdx.x * 256 + threadIdx.x;
    if (idx >= TOKENS * (long)FFNH) return;
    int c = (int)(idx & 4095);
    long bt = idx >> 12; int t = (int)(bt & 1023);
    float cur = in[idx];
    float pv = (t > 0)    ? in[idx - FFNH] : 0.f;
    float nx = (t < 1023) ? in[idx + FFNH] : 0.f;
    out[idx] = cur + 0.1f * (pv * w[c * 3] + cur * w[c * 3 + 1] + nx * w[c * 3 + 2]);
}

// ---------------- x1 = x + attn_out * (1 + 0.1*tanh(ca1)) -------------------
__global__ void x1_kernel(const float* __restrict__ x, const float* __restrict__ ao,
                          const float* __restrict__ ca1, float* __restrict__ x1) {
    long idx = (long)blockIdx.x * 256 + threadIdx.x;
    if (idx >= TOKENS * CDIM) return;
    x1[idx] = x[idx] + ao[idx] * (1.f + 0.1f * tanhf(ca1[idx]));
}

// ---------------- vit token scalar: sigmoid(h32 . w2) -----------------------
__global__ void vit_dot_kernel(const float* __restrict__ h32, const float* __restrict__ w2,
                               float* __restrict__ vit) {
    long tok = (long)blockIdx.x * 8 + (threadIdx.x >> 5);
    if (tok >= TOKENS) return;
    int lane = threadIdx.x & 31;
    float v = h32[tok * 32 + lane] * w2[lane];
    #pragma unroll
    for (int o = 16; o > 0; o >>= 1) v += __shfl_xor_sync(0xffffffffu, v, o);
    if (lane == 0) vit[tok] = 1.f / (1.f + expf(-v));
}

// ---------------- vit smooth + blend + threshold -----------------------------
__global__ void vit_smooth_kernel(const float* __restrict__ vit, float* __restrict__ vitf) {
    int idx = blockIdx.x * 256 + threadIdx.x;
    if (idx >= (int)TOKENS) return;
    int t = idx & 1023; int b0 = idx - t;
    float s = 0.f;
    #pragma unroll
    for (int d = -2; d <= 2; d++) {
        int tt = t + d;
        if (tt >= 0 && tt < 1024) s += vit[b0 + tt];
    }
    s *= 0.2f;
    float vv = 0.7f * vit[idx] + 0.3f * s;
    vitf[idx] = (vv > 0.3f) ? vv : 0.1f * vv;
}

// ---------------- final: out = x1 + mlp*(1+0.1*tanh(ca2))*vitf --------------
__global__ void final_kernel(const float* __restrict__ x1, const float* __restrict__ mlp,
                             const float* __restrict__ ca2, const float* __restrict__ vitf,
                             float* __restrict__ out) {
    long idx = (long)blockIdx.x * 256 + threadIdx.x;
    if (idx >= TOKENS * CDIM) return;
    long tok = idx >> 10;
    out[idx] = x1[idx] + mlp[idx] * (1.f + 0.1f * tanhf(ca2[idx])) * vitf[tok];
}

// ============================================================================
extern "C" void kernel_launch(void* const* d_in, const int* in_sizes, int n_in,
                              void* d_out, int out_size) {
    const float* x        = (const float*)d_in[0];
    const float* ve       = (const float*)d_in[1];
    const float* cosb     = (const float*)d_in[2];
    const float* sinb     = (const float*)d_in[3];
    const float* prev     = (const float*)d_in[4];
    const float* w_q      = (const float*)d_in[5];
    const float* w_k      = (const float*)d_in[6];
    const float* w_v      = (const float*)d_in[7];
    const float* w_o      = (const float*)d_in[8];
    const float* w_vegate = (const float*)d_in[9];
    const float* refine_w = (const float*)d_in[10];
    const float* alpha    = (const float*)d_in[11];
    const float* ca_pi    = (const float*)d_in[12];
    const float* ca_cw    = (const float*)d_in[13];
    const float* ca_po    = (const float*)d_in[14];
    const float* ffn_in   = (const float*)d_in[15];
    const float* ffn_cw   = (const float*)d_in[16];
    const float* ffn_out  = (const float*)d_in[17];
    const float* ffn_gate = (const float*)d_in[18];
    const float* vit_w1   = (const float*)d_in[19];
    const float* vit_w2   = (const float*)d_in[20];
    float* out = (float*)d_out;

    float *p_xn, *p_q, *p_k, *p_v, *p_att, *p_y, *p_ao, *p_cah, *p_cah2, *p_caout;
    float *p_x1, *p_xm, *p_ffh, *p_ffh2, *p_gate2, *p_mlp, *p_h32, *p_vit, *p_vitf;
    cudaGetSymbolAddress((void**)&p_xn,    g_xn);
    cudaGetSymbolAddress((void**)&p_q,     g_q);
    cudaGetSymbolAddress((void**)&p_k,     g_k);
    cudaGetSymbolAddress((void**)&p_v,     g_v);
    cudaGetSymbolAddress((void**)&p_att,   g_att);
    cudaGetSymbolAddress((void**)&p_y,     g_y);
    cudaGetSymbolAddress((void**)&p_ao,    g_ao);
    cudaGetSymbolAddress((void**)&p_cah,   g_cah);
    cudaGetSymbolAddress((void**)&p_cah2,  g_cah2);
    cudaGetSymbolAddress((void**)&p_caout, g_caout);
    cudaGetSymbolAddress((void**)&p_x1,    g_x1);
    cudaGetSymbolAddress((void**)&p_xm,    g_xm);
    cudaGetSymbolAddress((void**)&p_ffh,   g_ffh);
    cudaGetSymbolAddress((void**)&p_ffh2,  g_ffh2);
    cudaGetSymbolAddress((void**)&p_gate2, g_gate2);
    cudaGetSymbolAddress((void**)&p_mlp,   g_mlp);
    cudaGetSymbolAddress((void**)&p_h32,   g_h32);
    cudaGetSymbolAddress((void**)&p_vit,   g_vit);
    cudaGetSymbolAddress((void**)&p_vitf,  g_vitf);

    // 1. xn = rmsnorm(x)
    rmsnorm_kernel<<<4096, 256>>>(x, p_xn);
    // 2. q, k, v projections
    gemm_nt_kernel<<<dim3(16, 64), 256>>>(p_xn, w_q, p_q, 4096, 1024, 1024, 0, nullptr);
    gemm_nt_kernel<<<dim3(4, 64),  256>>>(p_xn, w_k, p_k, 4096, 256, 1024, 0, nullptr);
    gemm_nt_kernel<<<dim3(4, 64),  256>>>(p_xn, w_v, p_v, 4096, 256, 1024, 0, nullptr);
    // 3. ve gate into v
    vegate_kernel<<<4096, 256>>>(p_xn, ve, w_vegate, p_v);
    // 4. rope + qk-norm
    rope_rms_kernel<<<8192, 256>>>(p_q, cosb, sinb, 16);
    rope_rms_kernel<<<2048, 256>>>(p_k, cosb, sinb, 4);
    // 5. scores (+refine conv +mask), softmax, AV
    attn_score_kernel<<<dim3(16, 16, 64), 256>>>(p_q, p_k, prev, refine_w, alpha, p_att);
    softmax_kernel<<<65536, 256>>>(p_att);
    attn_av_kernel<<<dim3(16, 64), 256>>>(p_att, p_v, p_y);
    // 6. output projection
    gemm_nt_kernel<<<dim3(16, 64), 256>>>(p_y, w_o, p_ao, 4096, 1024, 1024, 0, nullptr);
    // 7. ca1 = ca_channel(x)
    gemm_nt_kernel<<<dim3(1, 64), 256>>>(x, ca_pi, p_cah, 4096, 32, 1024, 0, nullptr);
    ca_conv_gelu_kernel<<<512, 256>>>(p_cah, ca_cw, p_cah2);
    gemm_nt_kernel<<<dim3(16, 64), 256>>>(p_cah2, ca_po, p_caout, 4096, 1024, 32, 0, nullptr);
    // 8. x1
    x1_kernel<<<16384, 256>>>(x, p_ao, p_caout, p_x1);
    // 9. xm = rmsnorm(x1)
    rmsnorm_kernel<<<4096, 256>>>(p_x1, p_xm);
    // 10. h = relu(xm @ ffn_in^T)^2
    gemm_nt_kernel<<<dim3(64, 64), 256>>>(p_xm, ffn_in, p_ffh, 4096, 4096, 1024, 1, nullptr);
    // 11. temporal conv x4 (ping-pong, ends in p_ffh)
    ffn_tconv_kernel<<<65536, 256>>>(p_ffh,  ffn_cw, p_ffh2);
    ffn_tconv_kernel<<<65536, 256>>>(p_ffh2, ffn_cw, p_ffh);
    ffn_tconv_kernel<<<65536, 256>>>(p_ffh,  ffn_cw, p_ffh2);
    ffn_tconv_kernel<<<65536, 256>>>(p_ffh2, ffn_cw, p_ffh);
    // 12. gate2 = sigmoid(xm @ ffn_gate^T);  mlp = (h @ ffn_out^T) * gate2
    gemm_nt_kernel<<<dim3(16, 64), 256>>>(p_xm, ffn_gate, p_gate2, 4096, 1024, 1024, 2, nullptr);
    gemm_nt_kernel<<<dim3(16, 64), 256>>>(p_ffh, ffn_out, p_mlp, 4096, 1024, 4096, 4, p_gate2);
    // 13. ca2 = ca_channel(x1) (reuse buffers)
    gemm_nt_kernel<<<dim3(1, 64), 256>>>(p_x1, ca_pi, p_cah, 4096, 32, 1024, 0, nullptr);
    ca_conv_gelu_kernel<<<512, 256>>>(p_cah, ca_cw, p_cah2);
    gemm_nt_kernel<<<dim3(16, 64), 256>>>(p_cah2, ca_po, p_caout, 4096, 1024, 32, 0, nullptr);
    // 14. vit gate
    gemm_nt_kernel<<<dim3(1, 64), 256>>>(p_x1, vit_w1, p_h32, 4096, 32, 1024, 3, nullptr);
    vit_dot_kernel<<<512, 256>>>(p_h32, vit_w2, p_vit);
    vit_smooth_kernel<<<16, 256>>>(p_vit, p_vitf);
    // 15. final output
    final_kernel<<<16384, 256>>>(p_x1, p_mlp, p_caout, p_vitf, out);
}

// round 9
// speedup vs baseline: 1.9125x; 1.9125x over previous
#include <cuda_runtime.h>
#include <cuda_bf16.h>
#include <cstdint>
#include <math.h>

// Problem constants
#define TOKENS 4096L   // B*T
#define TSEQ   1024
#define CDIM   1024
#define NHEAD  16
#define NKV    4
#define HDIM   64
#define FFNH   4096

// ---------------- scratch (device globals; no allocation allowed) -----------
__device__ float g_xn   [TOKENS*CDIM];
__device__ float g_q    [TOKENS*CDIM];
__device__ float g_k    [TOKENS*256];
__device__ float g_v    [TOKENS*256];
__device__ float g_att  [64L*1024*1024];   // (B*NH, T, T)
__device__ float g_y    [TOKENS*CDIM];
__device__ float g_ao   [TOKENS*CDIM];
__device__ float g_cah  [TOKENS*32];
__device__ float g_cah2 [TOKENS*32];
__device__ float g_caout[TOKENS*CDIM];
__device__ float g_x1   [TOKENS*CDIM];
__device__ float g_xm   [TOKENS*CDIM];
__device__ float g_ffh  [TOKENS*FFNH];
__device__ float g_ffh2 [TOKENS*FFNH];
__device__ float g_gate2[TOKENS*CDIM];
__device__ float g_mlp  [TOKENS*CDIM];
__device__ float g_h32  [TOKENS*32];
__device__ float g_vit  [TOKENS];
__device__ float g_vitf [TOKENS];

// ======================= mma.sync helpers (baseline PTX, sm_80+) ============
__device__ __forceinline__ uint32_t smem_u32(const void* p) {
    uint32_t a;
    asm("{ .reg .u64 t; cvta.to.shared.u64 t, %1; cvt.u32.u64 %0, t; }" : "=r"(a) : "l"(p));
    return a;
}
__device__ __forceinline__ void ldmx4(uint32_t* r, uint32_t addr) {
    asm volatile("ldmatrix.sync.aligned.m8n8.x4.shared.b16 {%0,%1,%2,%3}, [%4];"
                 : "=r"(r[0]), "=r"(r[1]), "=r"(r[2]), "=r"(r[3]) : "r"(addr));
}
__device__ __forceinline__ void ldmx2(uint32_t* r, uint32_t addr) {
    asm volatile("ldmatrix.sync.aligned.m8n8.x2.shared.b16 {%0,%1}, [%2];"
                 : "=r"(r[0]), "=r"(r[1]) : "r"(addr));
}
__device__ __forceinline__ void mma16816(float* c, const uint32_t* a, const uint32_t* b) {
    asm volatile("mma.sync.aligned.m16n8k16.row.col.f32.bf16.bf16.f32 "
                 "{%0,%1,%2,%3}, {%4,%5,%6,%7}, {%8,%9}, {%0,%1,%2,%3};"
                 : "+f"(c[0]), "+f"(c[1]), "+f"(c[2]), "+f"(c[3])
                 : "r"(a[0]), "r"(a[1]), "r"(a[2]), "r"(a[3]), "r"(b[0]), "r"(b[1]));
}

// fp32 -> (hi bf16, lo bf16) packed pairs
__device__ __forceinline__ void cvt_pair(float a, float b, uint32_t& hi, uint32_t& lo) {
    __nv_bfloat16 h0 = __float2bfloat16(a);
    __nv_bfloat16 h1 = __float2bfloat16(b);
    __nv_bfloat16 l0 = __float2bfloat16(a - __bfloat162float(h0));
    __nv_bfloat16 l1 = __float2bfloat16(b - __bfloat162float(h1));
    hi = ((uint32_t)__bfloat16_as_ushort(h1) << 16) | __bfloat16_as_ushort(h0);
    lo = ((uint32_t)__bfloat16_as_ushort(l1) << 16) | __bfloat16_as_ushort(l0);
}

// fused multi-range weight / output / epilogue descriptor
struct Fuse {
    const float *W0, *W1, *W2;
    float *C0, *C1, *C2;
    int e0, e1, e2;          // exclusive range ends (global n)
    int ld0, ld1, ld2;       // output leading dims
    int md0, md1, md2;       // epilogue mode: 0 none, 1 relu^2, 2 sigmoid, 4 mul-aux
    const float* aux; int auxld;
};

__device__ __forceinline__ void epi_store(const Fuse& f, int gm, int gnn, float v) {
    int md, ldc, col; float* cp;
    if (gnn < f.e0)      { md = f.md0; cp = f.C0; ldc = f.ld0; col = gnn; }
    else if (gnn < f.e1) { md = f.md1; cp = f.C1; ldc = f.ld1; col = gnn - f.e0; }
    else                 { md = f.md2; cp = f.C2; ldc = f.ld2; col = gnn - f.e1; }
    if (md == 1)      { float r0 = fmaxf(v, 0.f); v = r0 * r0; }
    else if (md == 2) { v = 1.f / (1.f + __expf(-v)); }
    else if (md == 4) { v *= f.aux[(long)gm * f.auxld + gnn]; }
    cp[(long)gm * ldc + col] = v;
}

// ---------------- tensor-core GEMM via mma.sync: C = A[M,K] * W[N,K]^T ------
// 128x128 block tile, 8 warps (2x4), each warp 64x32, K-chunk 32.
// Split-bf16 3-term accumulation for ~fp32 accuracy.
#define KC 32
#define LDS_H 40   // padded halves per smem row (80B stride: conflict-free ldmatrix)
__global__ __launch_bounds__(256, 1)
void gemm_mma_kernel(const float* __restrict__ A, Fuse f, int K) {
    __shared__ __align__(16) __nv_bfloat16 sAh[128 * LDS_H];
    __shared__ __align__(16) __nv_bfloat16 sAl[128 * LDS_H];
    __shared__ __align__(16) __nv_bfloat16 sWh[128 * LDS_H];
    __shared__ __align__(16) __nv_bfloat16 sWl[128 * LDS_H];
    int tid = threadIdx.x, lane = tid & 31, warp = tid >> 5;
    int wm = warp >> 2, wn = warp & 3;        // warp tile: rows wm*64, cols wn*32
    int bm = blockIdx.y * 128, bn = blockIdx.x * 128;

    // loader mapping: each thread owns one row-half (16 cols) of A tile and W tile
    int lrow = tid >> 1, lcol = (tid & 1) * 16;
    const float* arow = A + (long)(bm + lrow) * K + lcol;
    int gn = bn + lrow;
    const float* wrow;
    if (gn < f.e0)      wrow = f.W0 + (long)gn * K;
    else if (gn < f.e1) wrow = f.W1 + (long)(gn - f.e0) * K;
    else                wrow = f.W2 + (long)(gn - f.e1) * K;
    wrow += lcol;

    uint32_t uAh = smem_u32(sAh), uAl = smem_u32(sAl);
    uint32_t uWh = smem_u32(sWh), uWl = smem_u32(sWl);

    float acc[4][4][4];
    #pragma unroll
    for (int i = 0; i < 4; i++)
        #pragma unroll
        for (int j = 0; j < 4; j++)
            #pragma unroll
            for (int r = 0; r < 4; r++) acc[i][j][r] = 0.f;

    int nc = K / KC;
    for (int c = 0; c < nc; c++) {
        // ---- load + convert chunk into smem ----
        {
            int so = lrow * LDS_H + lcol;
            #pragma unroll
            for (int q = 0; q < 4; q++) {
                float4 va = *(const float4*)(arow + c * KC + q * 4);
                uint32_t h0, l0, h1, l1;
                cvt_pair(va.x, va.y, h0, l0);
                cvt_pair(va.z, va.w, h1, l1);
                *(uint2*)(sAh + so + q * 4) = make_uint2(h0, h1);
                *(uint2*)(sAl + so + q * 4) = make_uint2(l0, l1);
            }
            #pragma unroll
            for (int q = 0; q < 4; q++) {
                float4 vw = *(const float4*)(wrow + c * KC + q * 4);
                uint32_t h0, l0, h1, l1;
                cvt_pair(vw.x, vw.y, h0, l0);
                cvt_pair(vw.z, vw.w, h1, l1);
                *(uint2*)(sWh + so + q * 4) = make_uint2(h0, h1);
                *(uint2*)(sWl + so + q * 4) = make_uint2(l0, l1);
            }
        }
        __syncthreads();
        // ---- compute: 2 k16 steps ----
        #pragma unroll
        for (int ks = 0; ks < 2; ks++) {
            int kk = ks * 16;
            uint32_t ah[4][4], al[4][4];
            #pragma unroll
            for (int mi = 0; mi < 4; mi++) {
                uint32_t off = (uint32_t)((wm * 64 + mi * 16 + (lane & 15)) * LDS_H
                                          + kk + 8 * (lane >> 4)) * 2;
                ldmx4(ah[mi], uAh + off);
                ldmx4(al[mi], uAl + off);
            }
            uint32_t bh[4][2], bl[4][2];
            #pragma unroll
            for (int nj = 0; nj < 4; nj++) {
                uint32_t off = (uint32_t)((wn * 32 + nj * 8 + (lane & 7)) * LDS_H
                                          + kk + 8 * ((lane >> 3) & 1)) * 2;
                ldmx2(bh[nj], uWh + off);
                ldmx2(bl[nj], uWl + off);
            }
            #pragma unroll
            for (int mi = 0; mi < 4; mi++)
                #pragma unroll
                for (int nj = 0; nj < 4; nj++) {
                    mma16816(acc[mi][nj], ah[mi], bh[nj]);
                    mma16816(acc[mi][nj], ah[mi], bl[nj]);
                    mma16816(acc[mi][nj], al[mi], bh[nj]);
                }
        }
        __syncthreads();
    }
    // ---- epilogue: C fragment: c0,c1 at (row, col..col+1), c2,c3 at row+8 ----
    #pragma unroll
    for (int mi = 0; mi < 4; mi++) {
        int r0 = bm + wm * 64 + mi * 16 + (lane >> 2);
        #pragma unroll
        for (int nj = 0; nj < 4; nj++) {
            int col = bn + wn * 32 + nj * 8 + (lane & 3) * 2;
            epi_store(f, r0,     col,     acc[mi][nj][0]);
            epi_store(f, r0,     col + 1, acc[mi][nj][1]);
            epi_store(f, r0 + 8, col,     acc[mi][nj][2]);
            epi_store(f, r0 + 8, col + 1, acc[mi][nj][3]);
        }
    }
}

// ---------------- rmsnorm: one block per row of C=1024 ----------------------
__global__ void rmsnorm_kernel(const float* __restrict__ x, float* __restrict__ o) {
    long row = blockIdx.x;
    const float* xr = x + row * CDIM;
    float* orow = o + row * CDIM;
    float ss = 0.f;
    for (int i = threadIdx.x; i < CDIM; i += 256) { float v = xr[i]; ss += v * v; }
    __shared__ float sh[256];
    sh[threadIdx.x] = ss; __syncthreads();
    for (int s = 128; s > 0; s >>= 1) { if (threadIdx.x < s) sh[threadIdx.x] += sh[threadIdx.x + s]; __syncthreads(); }
    float scale = rsqrtf(sh[0] / (float)CDIM + 1e-6f);
    for (int i = threadIdx.x; i < CDIM; i += 256) orow[i] = xr[i] * scale;
}

// ---------------- skinny SIMT GEMM (N<=64): ca_pi / vit_w1 ------------------
__global__ void gemm_nt_kernel(const float* __restrict__ A, const float* __restrict__ W,
                               float* __restrict__ C, int M, int N, int K,
                               int mode, const float* __restrict__ aux) {
    __shared__ float As[16][65];
    __shared__ float Ws[16][65];
    int bm = blockIdx.y * 64, bn = blockIdx.x * 64;
    int tid = threadIdx.x;
    int tx = tid & 15, ty = tid >> 4;
    float acc[4][4] = {};
    for (int k0 = 0; k0 < K; k0 += 16) {
        int kk = tid & 15;
        int r0 = tid >> 4;
        #pragma unroll
        for (int i = 0; i < 4; i++) {
            int m = r0 + 16 * i; int gm = bm + m;
            As[kk][m] = (gm < M) ? A[(long)gm * K + k0 + kk] : 0.f;
        }
        #pragma unroll
        for (int i = 0; i < 4; i++) {
            int n = r0 + 16 * i; int gn = bn + n;
            Ws[kk][n] = (gn < N) ? W[(long)gn * K + k0 + kk] : 0.f;
        }
        __syncthreads();
        #pragma unroll
        for (int k = 0; k < 16; k++) {
            float a[4], b[4];
            #pragma unroll
            for (int i = 0; i < 4; i++) a[i] = As[k][ty * 4 + i];
            #pragma unroll
            for (int j = 0; j < 4; j++) b[j] = Ws[k][tx * 4 + j];
            #pragma unroll
            for (int i = 0; i < 4; i++)
                #pragma unroll
                for (int j = 0; j < 4; j++) acc[i][j] += a[i] * b[j];
        }
        __syncthreads();
    }
    #pragma unroll
    for (int i = 0; i < 4; i++) {
        int gm = bm + ty * 4 + i; if (gm >= M) continue;
        #pragma unroll
        for (int j = 0; j < 4; j++) {
            int gn = bn + tx * 4 + j; if (gn >= N) continue;
            float v = acc[i][j];
            if (mode == 1)      { float r = fmaxf(v, 0.f); v = r * r; }
            else if (mode == 2) { v = 1.f / (1.f + __expf(-v)); }
            else if (mode == 3) { v = 0.5f * v * (1.f + erff(v * 0.70710678118654752f)); }
            else if (mode == 4) { v *= aux[(long)gm * N + gn]; }
            C[(long)gm * N + gn] = v;
        }
    }
}

// ---------------- ve gate fuse ----------------------------------------------
__global__ void vegate_kernel(const float* __restrict__ xn, const float* __restrict__ ve,
                              const float* __restrict__ wg, float* __restrict__ v) {
    long tok = blockIdx.x;
    __shared__ float g[4];
    __shared__ float xv[12];
    if (threadIdx.x < 12) xv[threadIdx.x] = xn[tok * CDIM + threadIdx.x];
    __syncthreads();
    if (threadIdx.x < 4) {
        float s = 0.f;
        #pragma unroll
        for (int j = 0; j < 12; j++) s += xv[j] * wg[threadIdx.x * 12 + j];
        g[threadIdx.x] = 3.f / (1.f + expf(-s));
    }
    __syncthreads();
    int i = threadIdx.x;
    v[tok * 256 + i] += g[i >> 6] * ve[tok * 256 + i];
}

// ---------------- rope + rmsnorm(HD=64) * 1.2 --------------------------------
__global__ void rope_rms_kernel(float* __restrict__ q, const float* __restrict__ cosb,
                                const float* __restrict__ sinb, int nh) {
    long idx = (long)blockIdx.x * 8 + (threadIdx.x >> 5);
    long total = TOKENS * nh;
    if (idx >= total) return;
    int lane = threadIdx.x & 31;
    long tok = idx / nh; int h = (int)(idx % nh);
    int t = (int)(tok & 1023);
    float* p = q + (tok * nh + h) * 64;
    float x1 = p[lane], x2 = p[lane + 32];
    float c = cosb[t * 32 + lane], s = sinb[t * 32 + lane];
    float r1 =  x1 * c + x2 * s;
    float r2 = -x1 * s + x2 * c;
    float ss = r1 * r1 + r2 * r2;
    #pragma unroll
    for (int o = 16; o > 0; o >>= 1) ss += __shfl_xor_sync(0xffffffffu, ss, o);
    float sc = rsqrtf(ss / 64.f + 1e-6f) * 1.2f;
    p[lane] = r1 * sc; p[lane + 32] = r2 * sc;
}

// ---------------- attention scores (skips fully-masked tiles) ----------------
__global__ void attn_score_kernel(const float* __restrict__ q, const float* __restrict__ k,
                                  const float* __restrict__ prev, const float* __restrict__ rw,
                                  const float* __restrict__ alphap, float* __restrict__ att) {
    int bh = blockIdx.z; int b = bh >> 4, h = bh & 15;
    int qt0 = blockIdx.y * 64, kt0 = blockIdx.x * 64;
    if (kt0 > qt0 + 63) return;   // never read downstream
    int tid = threadIdx.x, tx = tid & 15, ty = tid >> 4;
    long base = (long)bh * 1024 * 1024;
    __shared__ float smem[2 * 64 * 65];
    for (int i = tid; i < 64 * 64; i += 256) {
        int r = i >> 6, d = i & 63;
        smem[r * 65 + d] = q[((long)(b * 1024 + qt0 + r) * 16 + h) * 64 + d];
    }
    int kvh = h >> 2;
    for (int i = tid; i < 64 * 64; i += 256) {
        int r = i >> 6, d = i & 63;
        smem[64 * 65 + r * 65 + d] = k[((long)(b * 1024 + kt0 + r) * 4 + kvh) * 64 + d];
    }
    __syncthreads();
    float acc[4][4] = {};
    #pragma unroll 8
    for (int kk = 0; kk < 64; kk++) {
        float a[4], bv[4];
        #pragma unroll
        for (int i = 0; i < 4; i++) a[i]  = smem[(ty * 4 + i) * 65 + kk];
        #pragma unroll
        for (int j = 0; j < 4; j++) bv[j] = smem[64 * 65 + (tx * 4 + j) * 65 + kk];
        #pragma unroll
        for (int i = 0; i < 4; i++)
            #pragma unroll
            for (int j = 0; j < 4; j++) acc[i][j] += a[i] * bv[j];
    }
    __syncthreads();
    for (int i = tid; i < 66 * 66; i += 256) {
        int ii = i / 66, jj = i % 66;
        int gq = qt0 - 1 + ii, gk = kt0 - 1 + jj;
        float pv = (gq >= 0 && gq < 1024 && gk >= 0 && gk < 1024)
                       ? prev[base + (long)gq * 1024 + gk] : 0.f;
        smem[ii * 67 + jj] = pv;
    }
    __syncthreads();
    float w9[9];
    #pragma unroll
    for (int i = 0; i < 9; i++) w9[i] = rw[h * 9 + i];
    float alpha = alphap[0];
    #pragma unroll
    for (int i = 0; i < 4; i++) {
        int ql = ty * 4 + i;
        #pragma unroll
        for (int j = 0; j < 4; j++) {
            int kl = tx * 4 + j;
            float conv = 0.f;
            #pragma unroll
            for (int di = 0; di < 3; di++)
                #pragma unroll
                for (int dj = 0; dj < 3; dj++)
                    conv += smem[(ql + di) * 67 + kl + dj] * w9[di * 3 + dj];
            float sv = acc[i][j] * 0.125f + alpha * conv;
            int gq = qt0 + ql, gk = kt0 + kl;
            if (gk > gq) sv = -1e30f;
            att[base + (long)gq * 1024 + gk] = sv;
        }
    }
}

// ---------------- row softmax, causal-limited --------------------------------
__global__ void softmax_kernel(float* __restrict__ att) {
    long row = blockIdx.x;
    int qq = (int)(row & 1023);
    int klim = ((qq >> 6) + 1) << 6;     // only region written / read downstream
    float* p = att + row * 1024;
    __shared__ float sh[256];
    float m = -1e30f;
    for (int i = threadIdx.x; i < klim; i += 256) m = fmaxf(m, p[i]);
    sh[threadIdx.x] = m; __syncthreads();
    for (int s = 128; s > 0; s >>= 1) { if (threadIdx.x < s) sh[threadIdx.x] = fmaxf(sh[threadIdx.x], sh[threadIdx.x + s]); __syncthreads(); }
    m = sh[0]; __syncthreads();
    float sum = 0.f;
    for (int i = threadIdx.x; i < klim; i += 256) {
        float e = __expf(p[i] - m);
        p[i] = e; sum += e;
    }
    sh[threadIdx.x] = sum; __syncthreads();
    for (int s = 128; s > 0; s >>= 1) { if (threadIdx.x < s) sh[threadIdx.x] += sh[threadIdx.x + s]; __syncthreads(); }
    float inv = 1.f / sh[0];
    for (int i = threadIdx.x; i < klim; i += 256) p[i] *= inv;
}

// ---------------- y = aw @ v (causal-limited K loop) -------------------------
__global__ void attn_av_kernel(const float* __restrict__ aw, const float* __restrict__ v,
                               float* __restrict__ y) {
    int bh = blockIdx.y; int b = bh >> 4, h = bh & 15; int kvh = h >> 2;
    int qt0 = blockIdx.x * 64;
    long base = (long)bh * 1024 * 1024;
    __shared__ float As[64][17];
    __shared__ float Bs[16][65];
    int tid = threadIdx.x, tx = tid & 15, ty = tid >> 4;
    float acc[4][4] = {};
    int kmax = qt0 + 64;
    for (int k0 = 0; k0 < kmax; k0 += 16) {
        {
            int kk = tid & 15, m0 = tid >> 4;
            #pragma unroll
            for (int i = 0; i < 4; i++) {
                int m = m0 + 16 * i;
                As[m][kk] = aw[base + (long)(qt0 + m) * 1024 + k0 + kk];
            }
        }
        {
            int d = tid & 63, r0 = tid >> 6;
            #pragma unroll
            for (int i = 0; i < 4; i++) {
                int r = r0 + 4 * i;
                Bs[r][d] = v[((long)(b * 1024 + k0 + r) * 4 + kvh) * 64 + d];
            }
        }
        __syncthreads();
        #pragma unroll
        for (int kk = 0; kk < 16; kk++) {
            float a[4], bv[4];
            #pragma unroll
            for (int i = 0; i < 4; i++) a[i]  = As[ty * 4 + i][kk];
            #pragma unroll
            for (int j = 0; j < 4; j++) bv[j] = Bs[kk][tx * 4 + j];
            #pragma unroll
            for (int i = 0; i < 4; i++)
                #pragma unroll
                for (int j = 0; j < 4; j++) acc[i][j] += a[i] * bv[j];
        }
        __syncthreads();
    }
    #pragma unroll
    for (int i = 0; i < 4; i++)
        #pragma unroll
        for (int j = 0; j < 4; j++)
            y[((long)(b * 1024 + qt0 + ty * 4 + i) * 16 + h) * 64 + tx * 4 + j] = acc[i][j];
}

// ---------------- CA conv + exact gelu ---------------------------------------
__global__ void ca_conv_gelu_kernel(const float* __restrict__ in, const float* __restrict__ w,
                                    float* __restrict__ out) {
    long idx = (long)blockIdx.x * 256 + threadIdx.x;
    if (idx >= TOKENS * 32) return;
    int c = (int)(idx & 31);
    long bt = idx >> 5; int t = (int)(bt & 1023);
    float cur = in[idx];
    float pv = (t > 0)    ? in[idx - 32] : 0.f;
    float nx = (t < 1023) ? in[idx + 32] : 0.f;
    float h = cur + 0.1f * (pv * w[c * 3] + cur * w[c * 3 + 1] + nx * w[c * 3 + 2]);
    out[idx] = 0.5f * h * (1.f + erff(h * 0.70710678118654752f));
}

// ---------------- fused 4x temporal dwconv (shared-memory ping-pong) ---------
__global__ void ffn_tconv4_kernel(const float* __restrict__ in, const float* __restrict__ w,
                                  float* __restrict__ out) {
    __shared__ float S0[72][33];
    __shared__ float S1[72][33];
    int c0 = blockIdx.x * 32;
    int t0 = blockIdx.y * 64;
    int b  = blockIdx.z;
    int c = threadIdx.x & 31, tg = threadIdx.x >> 5;  // 8 t-groups
    float w0 = w[(c0 + c) * 3], w1 = w[(c0 + c) * 3 + 1], w2 = w[(c0 + c) * 3 + 2];
    for (int tt = tg; tt < 72; tt += 8) {
        int gt = t0 - 4 + tt;
        S0[tt][c] = (gt >= 0 && gt < 1024)
                        ? in[((long)(b * 1024 + gt)) * FFNH + c0 + c] : 0.f;
    }
    __syncthreads();
    float (*Sa)[33] = S0; float (*Sb)[33] = S1;
    #pragma unroll
    for (int p = 1; p <= 4; p++) {
        for (int tt = tg; tt < 72; tt += 8) {
            if (tt >= p && tt < 72 - p) {
                float pv = Sa[tt - 1][c], cur = Sa[tt][c], nx = Sa[tt + 1][c];
                float v = cur + 0.1f * (w0 * pv + w1 * cur + w2 * nx);
                int gt = t0 - 4 + tt;
                if (gt < 0 || gt >= 1024) v = 0.f;
                Sb[tt][c] = v;
            }
        }
        __syncthreads();
        float (*tmp)[33] = Sa; Sa = Sb; Sb = tmp;
    }
    for (int tt = tg; tt < 72; tt += 8) {
        if (tt >= 4 && tt < 68) {
            int gt = t0 - 4 + tt;
            out[((long)(b * 1024 + gt)) * FFNH + c0 + c] = Sa[tt][c];
        }
    }
}

// ---------------- small elementwise kernels ----------------------------------
__global__ void x1_kernel(const float* __restrict__ x, const float* __restrict__ ao,
                          const float* __restrict__ ca1, float* __restrict__ x1) {
    long idx = (long)blockIdx.x * 256 + threadIdx.x;
    if (idx >= TOKENS * CDIM) return;
    x1[idx] = x[idx] + ao[idx] * (1.f + 0.1f * tanhf(ca1[idx]));
}
__global__ void vit_dot_kernel(const float* __restrict__ h32, const float* __restrict__ w2,
                               float* __restrict__ vit) {
    long tok = (long)blockIdx.x * 8 + (threadIdx.x >> 5);
    if (tok >= TOKENS) return;
    int lane = threadIdx.x & 31;
    float v = h32[tok * 32 + lane] * w2[lane];
    #pragma unroll
    for (int o = 16; o > 0; o >>= 1) v += __shfl_xor_sync(0xffffffffu, v, o);
    if (lane == 0) vit[tok] = 1.f / (1.f + expf(-v));
}
__global__ void vit_smooth_kernel(const float* __restrict__ vit, float* __restrict__ vitf) {
    int idx = blockIdx.x * 256 + threadIdx.x;
    if (idx >= (int)TOKENS) return;
    int t = idx & 1023; int b0 = idx - t;
    float s = 0.f;
    #pragma unroll
    for (int d = -2; d <= 2; d++) {
        int tt = t + d;
        if (tt >= 0 && tt < 1024) s += vit[b0 + tt];
    }
    s *= 0.2f;
    float vv = 0.7f * vit[idx] + 0.3f * s;
    vitf[idx] = (vv > 0.3f) ? vv : 0.1f * vv;
}
__global__ void final_kernel(const float* __restrict__ x1, const float* __restrict__ mlp,
                             const float* __restrict__ ca2, const float* __restrict__ vitf,
                             float* __restrict__ out) {
    long idx = (long)blockIdx.x * 256 + threadIdx.x;
    if (idx >= TOKENS * CDIM) return;
    long tok = idx >> 10;
    out[idx] = x1[idx] + mlp[idx] * (1.f + 0.1f * tanhf(ca2[idx])) * vitf[tok];
}

// ============================================================================
extern "C" void kernel_launch(void* const* d_in, const int* in_sizes, int n_in,
                              void* d_out, int out_size) {
    const float* x        = (const float*)d_in[0];
    const float* ve       = (const float*)d_in[1];
    const float* cosb     = (const float*)d_in[2];
    const float* sinb     = (const float*)d_in[3];
    const float* prev     = (const float*)d_in[4];
    const float* w_q      = (const float*)d_in[5];
    const float* w_k      = (const float*)d_in[6];
    const float* w_v      = (const float*)d_in[7];
    const float* w_o      = (const float*)d_in[8];
    const float* w_vegate = (const float*)d_in[9];
    const float* refine_w = (const float*)d_in[10];
    const float* alpha    = (const float*)d_in[11];
    const float* ca_pi    = (const float*)d_in[12];
    const float* ca_cw    = (const float*)d_in[13];
    const float* ca_po    = (const float*)d_in[14];
    const float* ffn_in   = (const float*)d_in[15];
    const float* ffn_cw   = (const float*)d_in[16];
    const float* ffn_out  = (const float*)d_in[17];
    const float* ffn_gate = (const float*)d_in[18];
    const float* vit_w1   = (const float*)d_in[19];
    const float* vit_w2   = (const float*)d_in[20];
    float* out = (float*)d_out;

    float *p_xn, *p_q, *p_k, *p_v, *p_att, *p_y, *p_ao, *p_cah, *p_cah2, *p_caout;
    float *p_x1, *p_xm, *p_ffh, *p_ffh2, *p_gate2, *p_mlp, *p_h32, *p_vit, *p_vitf;
    cudaGetSymbolAddress((void**)&p_xn,    g_xn);
    cudaGetSymbolAddress((void**)&p_q,     g_q);
    cudaGetSymbolAddress((void**)&p_k,     g_k);
    cudaGetSymbolAddress((void**)&p_v,     g_v);
    cudaGetSymbolAddress((void**)&p_att,   g_att);
    cudaGetSymbolAddress((void**)&p_y,     g_y);
    cudaGetSymbolAddress((void**)&p_ao,    g_ao);
    cudaGetSymbolAddress((void**)&p_cah,   g_cah);
    cudaGetSymbolAddress((void**)&p_cah2,  g_cah2);
    cudaGetSymbolAddress((void**)&p_caout, g_caout);
    cudaGetSymbolAddress((void**)&p_x1,    g_x1);
    cudaGetSymbolAddress((void**)&p_xm,    g_xm);
    cudaGetSymbolAddress((void**)&p_ffh,   g_ffh);
    cudaGetSymbolAddress((void**)&p_ffh2,  g_ffh2);
    cudaGetSymbolAddress((void**)&p_gate2, g_gate2);
    cudaGetSymbolAddress((void**)&p_mlp,   g_mlp);
    cudaGetSymbolAddress((void**)&p_h32,   g_h32);
    cudaGetSymbolAddress((void**)&p_vit,   g_vit);
    cudaGetSymbolAddress((void**)&p_vitf,  g_vitf);

    // 1. xn = rmsnorm(x)
    rmsnorm_kernel<<<4096, 256>>>(x, p_xn);

    // 2. fused QKV projection (mma.sync): N = 1024 | 256 | 256
    {
        Fuse f;
        f.W0 = w_q;  f.W1 = w_k;  f.W2 = w_v;
        f.C0 = p_q;  f.C1 = p_k;  f.C2 = p_v;
        f.e0 = 1024; f.e1 = 1280; f.e2 = 1536;
        f.ld0 = 1024; f.ld1 = 256; f.ld2 = 256;
        f.md0 = 0; f.md1 = 0; f.md2 = 0;
        f.aux = nullptr; f.auxld = 0;
        gemm_mma_kernel<<<dim3(12, 32), 256>>>(p_xn, f, 1024);
    }
    // 3. ve gate into v
    vegate_kernel<<<4096, 256>>>(p_xn, ve, w_vegate, p_v);
    // 4. rope + qk-norm
    rope_rms_kernel<<<8192, 256>>>(p_q, cosb, sinb, 16);
    rope_rms_kernel<<<2048, 256>>>(p_k, cosb, sinb, 4);
    // 5. scores (+refine conv +mask), softmax (causal-limited), AV
    attn_score_kernel<<<dim3(16, 16, 64), 256>>>(p_q, p_k, prev, refine_w, alpha, p_att);
    softmax_kernel<<<65536, 256>>>(p_att);
    attn_av_kernel<<<dim3(16, 64), 256>>>(p_att, p_v, p_y);
    // 6. output projection
    {
        Fuse f;
        f.W0 = f.W1 = f.W2 = w_o;
        f.C0 = f.C1 = f.C2 = p_ao;
        f.e0 = f.e1 = f.e2 = 1024;
        f.ld0 = f.ld1 = f.ld2 = 1024;
        f.md0 = f.md1 = f.md2 = 0;
        f.aux = nullptr; f.auxld = 0;
        gemm_mma_kernel<<<dim3(8, 32), 256>>>(p_y, f, 1024);
    }
    // 7. ca1 = ca_channel(x)
    gemm_nt_kernel<<<dim3(1, 64), 256>>>(x, ca_pi, p_cah, 4096, 32, 1024, 0, nullptr);
    ca_conv_gelu_kernel<<<512, 256>>>(p_cah, ca_cw, p_cah2);
    {
        Fuse f;
        f.W0 = f.W1 = f.W2 = ca_po;
        f.C0 = f.C1 = f.C2 = p_caout;
        f.e0 = f.e1 = f.e2 = 1024;
        f.ld0 = f.ld1 = f.ld2 = 1024;
        f.md0 = f.md1 = f.md2 = 0;
        f.aux = nullptr; f.auxld = 0;
        gemm_mma_kernel<<<dim3(8, 32), 256>>>(p_cah2, f, 32);
    }
    // 8. x1
    x1_kernel<<<16384, 256>>>(x, p_ao, p_caout, p_x1);
    // 9. xm = rmsnorm(x1)
    rmsnorm_kernel<<<4096, 256>>>(p_x1, p_xm);
    // 10. fused FFN up + gate: relu^2 into ffh, sigmoid into gate2
    {
        Fuse f;
        f.W0 = ffn_in;   f.W1 = ffn_gate; f.W2 = ffn_gate;
        f.C0 = p_ffh;    f.C1 = p_gate2;  f.C2 = p_gate2;
        f.e0 = 4096;     f.e1 = 5120;     f.e2 = 5120;
        f.ld0 = 4096;    f.ld1 = 1024;    f.ld2 = 1024;
        f.md0 = 1;       f.md1 = 2;       f.md2 = 2;
        f.aux = nullptr; f.auxld = 0;
        gemm_mma_kernel<<<dim3(40, 32), 256>>>(p_xm, f, 1024);
    }
    // 11. fused 4x temporal conv: ffh -> ffh2
    ffn_tconv4_kernel<<<dim3(128, 16, 4), 256>>>(p_ffh, ffn_cw, p_ffh2);
    // 12. mlp = (h @ ffn_out^T) * gate2
    {
        Fuse f;
        f.W0 = f.W1 = f.W2 = ffn_out;
        f.C0 = f.C1 = f.C2 = p_mlp;
        f.e0 = f.e1 = f.e2 = 1024;
        f.ld0 = f.ld1 = f.ld2 = 1024;
        f.md0 = f.md1 = f.md2 = 4;
        f.aux = p_gate2; f.auxld = 1024;
        gemm_mma_kernel<<<dim3(8, 32), 256>>>(p_ffh2, f, 4096);
    }
    // 13. ca2 = ca_channel(x1)
    gemm_nt_kernel<<<dim3(1, 64), 256>>>(p_x1, ca_pi, p_cah, 4096, 32, 1024, 0, nullptr);
    ca_conv_gelu_kernel<<<512, 256>>>(p_cah, ca_cw, p_cah2);
    {
        Fuse f;
        f.W0 = f.W1 = f.W2 = ca_po;
        f.C0 = f.C1 = f.C2 = p_caout;
        f.e0 = f.e1 = f.e2 = 1024;
        f.ld0 = f.ld1 = f.ld2 = 1024;
        f.md0 = f.md1 = f.md2 = 0;
        f.aux = nullptr; f.auxld = 0;
        gemm_mma_kernel<<<dim3(8, 32), 256>>>(p_cah2, f, 32);
    }
    // 14. vit gate
    gemm_nt_kernel<<<dim3(1, 64), 256>>>(p_x1, vit_w1, p_h32, 4096, 32, 1024, 3, nullptr);
    vit_dot_kernel<<<512, 256>>>(p_h32, vit_w2, p_vit);
    vit_smooth_kernel<<<16, 256>>>(p_vit, p_vitf);
    // 15. final output
    final_kernel<<<16384, 256>>>(p_x1, p_mlp, p_caout, p_vitf, out);
}